// round 10
// baseline (speedup 1.0000x reference)
#include <cuda_runtime.h>
#include <math.h>

#define B_  4
#define S_  1920
#define D_  1024
#define H_  8
#define L_  6
#define BLK_ 64
#define NB_ 30
#define NI_ 28
#define R_  3
#define FF_ 4096
#define DH_ 128
#define NLBL_ 1000
#define BS_ (B_*S_)
#define NEGF (-1.0e9f)

// ---------------- scratch (device globals; no allocation allowed) ------------
__device__ float g_h [(size_t)BS_*D_];
__device__ float g_t [(size_t)BS_*D_];
__device__ float g_q [(size_t)BS_*D_];
__device__ float g_k [(size_t)BS_*D_];
__device__ float g_v [(size_t)BS_*D_];
__device__ float g_attn[(size_t)BS_*D_];
__device__ float g_ff[(size_t)BS_*FF_];
__device__ float g_cls[B_*512];

// ---------------- helpers ----------------------------------------------------
__device__ __forceinline__ float gelu_f(float z) {
    // jax.nn.gelu approximate=True (tanh form)
    float z3 = z*z*z;
    return 0.5f*z*(1.0f + tanhf(0.7978845608028654f*(z + 0.044715f*z3)));
}

__device__ __forceinline__ float blockSum256(float v, float* red) {
    #pragma unroll
    for (int o = 16; o; o >>= 1) v += __shfl_xor_sync(0xffffffffu, v, o);
    __syncthreads();
    if ((threadIdx.x & 31) == 0) red[threadIdx.x >> 5] = v;
    __syncthreads();
    if (threadIdx.x == 0) {
        float t = 0.f;
        #pragma unroll
        for (int i = 0; i < 8; i++) t += red[i];
        red[8] = t;
    }
    __syncthreads();
    return red[8];
}

// ---------------- embedding: h = LN(x + pos_emb) ------------------------------
__global__ void embed_kernel(const float* __restrict__ x, const float* __restrict__ pos,
                             const float* __restrict__ gm, const float* __restrict__ bt) {
    __shared__ float red[9];
    int row = blockIdx.x;            // 0..BS_-1
    int s   = row % S_;
    const float* xr = x + (size_t)row*D_;
    const float* pr = pos + (size_t)s*D_;
    int t = threadIdx.x;             // 256 threads
    float v[4];
    #pragma unroll
    for (int j = 0; j < 4; j++) { int c = t + j*256; v[j] = xr[c] + pr[c]; }
    float su = v[0]+v[1]+v[2]+v[3];
    float mean = blockSum256(su, red) * (1.0f/(float)D_);
    float d[4], sq = 0.f;
    #pragma unroll
    for (int j = 0; j < 4; j++) { d[j] = v[j] - mean; sq += d[j]*d[j]; }
    float var = blockSum256(sq, red) * (1.0f/(float)D_);
    float rs = rsqrtf(var + 1e-12f);
    float* hr = g_h + (size_t)row*D_;
    #pragma unroll
    for (int j = 0; j < 4; j++) { int c = t + j*256; hr[c] = d[j]*rs*gm[c] + bt[c]; }
}

// ---------------- layernorm in place -----------------------------------------
__global__ void ln_kernel(float* __restrict__ x,
                          const float* __restrict__ gm, const float* __restrict__ bt) {
    __shared__ float red[9];
    int row = blockIdx.x;
    float* xr = x + (size_t)row*D_;
    int t = threadIdx.x;             // 256
    float v[4];
    #pragma unroll
    for (int j = 0; j < 4; j++) v[j] = xr[t + j*256];
    float su = v[0]+v[1]+v[2]+v[3];
    float mean = blockSum256(su, red) * (1.0f/(float)D_);
    float d[4], sq = 0.f;
    #pragma unroll
    for (int j = 0; j < 4; j++) { d[j] = v[j] - mean; sq += d[j]*d[j]; }
    float var = blockSum256(sq, red) * (1.0f/(float)D_);
    float rs = rsqrtf(var + 1e-12f);
    #pragma unroll
    for (int j = 0; j < 4; j++) { int c = t + j*256; xr[c] = d[j]*rs*gm[c] + bt[c]; }
}

// ---------------- SGEMM: C = A(MxK) @ Bw(KxN) + bias [+res | gelu] -----------
// BM=BN=128, BK=8, 256 threads, 8x8 micro-tile
__global__ __launch_bounds__(256, 2)
void sgemm_kernel(const float* __restrict__ A, const float* __restrict__ Bw,
                  const float* __restrict__ bias, const float* __restrict__ res,
                  float* __restrict__ C, int M, int N, int K, int epi) {
    __shared__ float As[8][132];
    __shared__ float Bs[8][128];
    int bm = blockIdx.y * 128, bn = blockIdx.x * 128;
    int tid = threadIdx.x;
    int arow = tid >> 1, acol = (tid & 1) << 2;
    int brow = tid >> 5, bcol = (tid & 31) << 2;
    int tx = tid & 15, ty = tid >> 4;
    const float* Ap = A + (size_t)(bm + arow)*K + acol;
    const float* Bp = Bw + (size_t)brow*N + bn + bcol;
    float acc[8][8];
    #pragma unroll
    for (int i = 0; i < 8; i++)
        #pragma unroll
        for (int j = 0; j < 8; j++) acc[i][j] = 0.f;
    int nk = K >> 3;
    for (int kt = 0; kt < nk; kt++) {
        float4 a4 = *(const float4*)Ap;
        float4 b4 = *(const float4*)Bp;
        As[acol+0][arow] = a4.x; As[acol+1][arow] = a4.y;
        As[acol+2][arow] = a4.z; As[acol+3][arow] = a4.w;
        *(float4*)&Bs[brow][bcol] = b4;
        __syncthreads();
        #pragma unroll
        for (int kk = 0; kk < 8; kk++) {
            float fa[8], fb[8];
            *(float4*)&fa[0] = *(const float4*)&As[kk][ty*8];
            *(float4*)&fa[4] = *(const float4*)&As[kk][ty*8+4];
            *(float4*)&fb[0] = *(const float4*)&Bs[kk][tx*8];
            *(float4*)&fb[4] = *(const float4*)&Bs[kk][tx*8+4];
            #pragma unroll
            for (int i = 0; i < 8; i++)
                #pragma unroll
                for (int j = 0; j < 8; j++)
                    acc[i][j] += fa[i]*fb[j];
        }
        __syncthreads();
        Ap += 8; Bp += (size_t)8*N;
    }
    #pragma unroll
    for (int i = 0; i < 8; i++) {
        int r = bm + ty*8 + i;
        size_t off = (size_t)r*N + bn + tx*8;
        #pragma unroll
        for (int j = 0; j < 8; j++) {
            int cidx = bn + tx*8 + j;
            float vv = acc[i][j] + bias[cidx];
            if (epi == 1)      vv += res[off + j];
            else if (epi == 2) vv = gelu_f(vv);
            C[off + j] = vv;
        }
    }
}

// ---------------- inner-block BigBird attention --------------------------------
// grid (NI_, H_, B_), 256 threads. Dynamic smem:
//   Qs 64x129 | KV 64x129 | Sc 64x516   = 49536 floats = 198144 B
#define SMEM_INNER (49536*4)
__global__ void attn_inner_kernel(const float* __restrict__ mask, const int* __restrict__ rnd) {
    extern __shared__ float sm[];
    float* Qs = sm;
    float* KV = sm + 64*129;
    float* Sc = sm + 2*64*129;
    __shared__ int   kblk[8];
    __shared__ float keepm[8];

    const int i = blockIdx.x, h = blockIdx.y, b = blockIdx.z;
    const int tid = threadIdx.x;
    const int tok0 = (i + 1) * BLK_;
    const float scale = 0.08838834764831845f;   // 1/sqrt(128)

    if (tid == 0) {
        int idx8[8];
        idx8[0] = 0; idx8[1] = NB_-1; idx8[2] = i; idx8[3] = i+1; idx8[4] = i+2;
        idx8[5] = rnd[(h*NI_ + i)*R_ + 0];
        idx8[6] = rnd[(h*NI_ + i)*R_ + 1];
        idx8[7] = rnd[(h*NI_ + i)*R_ + 2];
        #pragma unroll
        for (int j = 0; j < 8; j++) {
            float kp = 1.f;
            for (int j2 = 0; j2 < j; j2++) if (idx8[j2] == idx8[j]) kp = 0.f;
            kblk[j] = idx8[j]; keepm[j] = kp;
        }
    }
    // load Q (scaled)
    for (int t = tid; t < 64*32; t += 256) {
        int r = t >> 5, c = (t & 31) << 2;
        float4 v4 = *(const float4*)(g_q + ((size_t)(b*S_ + tok0 + r))*D_ + h*DH_ + c);
        float* dst = Qs + r*129 + c;
        dst[0] = v4.x*scale; dst[1] = v4.y*scale; dst[2] = v4.z*scale; dst[3] = v4.w*scale;
    }
    __syncthreads();

    const int ty = tid >> 4, tx = tid & 15;

    // ---- scores: 8 key blocks of 64 keys
    for (int jb = 0; jb < 8; jb++) {
        int kt0 = kblk[jb] * BLK_;
        for (int t = tid; t < 64*32; t += 256) {
            int r = t >> 5, c = (t & 31) << 2;
            float4 v4 = *(const float4*)(g_k + ((size_t)(b*S_ + kt0 + r))*D_ + h*DH_ + c);
            float* dst = KV + r*129 + c;
            dst[0] = v4.x; dst[1] = v4.y; dst[2] = v4.z; dst[3] = v4.w;
        }
        __syncthreads();
        float acc[4][4];
        #pragma unroll
        for (int a = 0; a < 4; a++)
            #pragma unroll
            for (int c2 = 0; c2 < 4; c2++) acc[a][c2] = 0.f;
        #pragma unroll 4
        for (int d = 0; d < 128; d++) {
            float fa[4], fb[4];
            #pragma unroll
            for (int u = 0; u < 4; u++) fa[u] = Qs[(ty*4+u)*129 + d];
            #pragma unroll
            for (int u = 0; u < 4; u++) fb[u] = KV[(tx*4+u)*129 + d];
            #pragma unroll
            for (int a = 0; a < 4; a++)
                #pragma unroll
                for (int c2 = 0; c2 < 4; c2++) acc[a][c2] += fa[a]*fb[c2];
        }
        float km = keepm[jb];
        #pragma unroll
        for (int c2 = 0; c2 < 4; c2++) {
            int kk = tx*4 + c2;
            float mg = km * mask[b*S_ + kt0 + kk];
            #pragma unroll
            for (int a = 0; a < 4; a++)
                Sc[(ty*4+a)*516 + jb*64 + kk] = (mg > 0.f) ? acc[a][c2] : NEGF;
        }
        __syncthreads();
    }

    // ---- softmax per row over 512 keys (4 threads per row)
    {
        int row = tid >> 2, l4 = tid & 3;
        float* Sr = Sc + row*516;
        float mx = -3.0e38f;
        for (int kk = l4; kk < 512; kk += 4) mx = fmaxf(mx, Sr[kk]);
        mx = fmaxf(mx, __shfl_xor_sync(0xffffffffu, mx, 1));
        mx = fmaxf(mx, __shfl_xor_sync(0xffffffffu, mx, 2));
        float su = 0.f;
        for (int kk = l4; kk < 512; kk += 4) {
            float p = __expf(Sr[kk] - mx);
            Sr[kk] = p; su += p;
        }
        su += __shfl_xor_sync(0xffffffffu, su, 1);
        su += __shfl_xor_sync(0xffffffffu, su, 2);
        float inv = 1.0f / su;
        for (int kk = l4; kk < 512; kk += 4) Sr[kk] *= inv;
    }
    __syncthreads();

    // ---- O = P @ V : 64x128, micro 4 rows x 8 cols
    float oacc[4][8];
    #pragma unroll
    for (int a = 0; a < 4; a++)
        #pragma unroll
        for (int c2 = 0; c2 < 8; c2++) oacc[a][c2] = 0.f;
    for (int jb = 0; jb < 8; jb++) {
        int kt0 = kblk[jb] * BLK_;
        for (int t = tid; t < 64*32; t += 256) {
            int r = t >> 5, c = (t & 31) << 2;
            float4 v4 = *(const float4*)(g_v + ((size_t)(b*S_ + kt0 + r))*D_ + h*DH_ + c);
            float* dst = KV + r*129 + c;
            dst[0] = v4.x; dst[1] = v4.y; dst[2] = v4.z; dst[3] = v4.w;
        }
        __syncthreads();
        #pragma unroll 2
        for (int kk = 0; kk < 64; kk++) {
            float pa[4], vb[8];
            #pragma unroll
            for (int u = 0; u < 4; u++) pa[u] = Sc[(ty*4+u)*516 + jb*64 + kk];
            #pragma unroll
            for (int u = 0; u < 8; u++) vb[u] = KV[kk*129 + tx*8 + u];
            #pragma unroll
            for (int a = 0; a < 4; a++)
                #pragma unroll
                for (int c2 = 0; c2 < 8; c2++) oacc[a][c2] += pa[a]*vb[c2];
        }
        __syncthreads();
    }
    #pragma unroll
    for (int a = 0; a < 4; a++) {
        int tok = tok0 + ty*4 + a;
        float* dst = g_attn + ((size_t)(b*S_ + tok))*D_ + h*DH_ + tx*8;
        #pragma unroll
        for (int c2 = 0; c2 < 8; c2++) dst[c2] = oacc[a][c2];
    }
}

// ---------------- global-block attention (flash over 30 chunks) ---------------
// grid (4 qsub, 2 g, B_*H_), 256 threads.
// smem: Qs 16x129 | Ks 64x129 | Vs 64x129 | Ss 16x68 | m/l/corr 16 each
#define SMEM_GLOB ((16*129 + 2*64*129 + 16*68 + 48)*4)
__global__ void attn_global_kernel(const float* __restrict__ mask) {
    extern __shared__ float sm[];
    float* Qs = sm;
    float* Ks = Qs + 16*129;
    float* Vs = Ks + 64*129;
    float* Ss = Vs + 64*129;
    float* mrow = Ss + 16*68;
    float* lrow = mrow + 16;
    float* crow = lrow + 16;

    const int qs = blockIdx.x;
    const int g  = blockIdx.y;
    const int b  = blockIdx.z >> 3, h = blockIdx.z & 7;
    const int tid = threadIdx.x;
    const int tok0 = (g == 0 ? 0 : (NB_-1)*BLK_) + qs*16;
    const float scale = 0.08838834764831845f;

    for (int t = tid; t < 16*32; t += 256) {
        int r = t >> 5, c = (t & 31) << 2;
        float4 v4 = *(const float4*)(g_q + ((size_t)(b*S_ + tok0 + r))*D_ + h*DH_ + c);
        float* dst = Qs + r*129 + c;
        dst[0] = v4.x*scale; dst[1] = v4.y*scale; dst[2] = v4.z*scale; dst[3] = v4.w*scale;
    }
    if (tid < 16) { mrow[tid] = -3.0e38f; lrow[tid] = 0.f; }
    __syncthreads();

    const int row = tid >> 4, tx = tid & 15;
    float oacc[8];
    #pragma unroll
    for (int u = 0; u < 8; u++) oacc[u] = 0.f;

    for (int cb = 0; cb < NB_; cb++) {
        int kt0 = cb * BLK_;
        for (int t = tid; t < 64*32; t += 256) {
            int r = t >> 5, c = (t & 31) << 2;
            size_t gi = ((size_t)(b*S_ + kt0 + r))*D_ + h*DH_ + c;
            float4 k4 = *(const float4*)(g_k + gi);
            float4 v4 = *(const float4*)(g_v + gi);
            float* dk = Ks + r*129 + c;
            float* dv = Vs + r*129 + c;
            dk[0]=k4.x; dk[1]=k4.y; dk[2]=k4.z; dk[3]=k4.w;
            dv[0]=v4.x; dv[1]=v4.y; dv[2]=v4.z; dv[3]=v4.w;
        }
        __syncthreads();
        // scores: each thread 1 row x 4 keys
        float sc4[4] = {0.f, 0.f, 0.f, 0.f};
        #pragma unroll 4
        for (int d = 0; d < 128; d++) {
            float qa = Qs[row*129 + d];
            #pragma unroll
            for (int u = 0; u < 4; u++) sc4[u] += qa * Ks[(tx*4+u)*129 + d];
        }
        #pragma unroll
        for (int u = 0; u < 4; u++) {
            int kk = tx*4 + u;
            float mg = mask[b*S_ + kt0 + kk];
            Ss[row*68 + kk] = (mg > 0.f) ? sc4[u] : NEGF;
        }
        __syncthreads();
        if (tid < 16) {
            float* Sr = Ss + tid*68;
            float cmax = -3.0e38f;
            for (int kk = 0; kk < 64; kk++) cmax = fmaxf(cmax, Sr[kk]);
            float m0 = mrow[tid];
            float nm = fmaxf(m0, cmax);
            float cr = __expf(m0 - nm);
            float sn = 0.f;
            for (int kk = 0; kk < 64; kk++) {
                float p = __expf(Sr[kk] - nm);
                Sr[kk] = p; sn += p;
            }
            lrow[tid] = lrow[tid]*cr + sn;
            mrow[tid] = nm;
            crow[tid] = cr;
        }
        __syncthreads();
        float cr = crow[row];
        #pragma unroll
        for (int u = 0; u < 8; u++) oacc[u] *= cr;
        #pragma unroll 2
        for (int kk = 0; kk < 64; kk++) {
            float p = Ss[row*68 + kk];
            #pragma unroll
            for (int u = 0; u < 8; u++) oacc[u] += p * Vs[kk*129 + tx*8 + u];
        }
        __syncthreads();
    }
    float inv = 1.0f / lrow[row];
    float* dst = g_attn + ((size_t)(b*S_ + tok0 + row))*D_ + h*DH_ + tx*8;
    #pragma unroll
    for (int u = 0; u < 8; u++) dst[u] = oacc[u]*inv;
}

// ---------------- classifier ---------------------------------------------------
__global__ void cls1_kernel(const float* __restrict__ hbuf, const float* __restrict__ Wc1,
                            const float* __restrict__ bc1) {
    __shared__ float hs[1024];
    int b = blockIdx.x, t = threadIdx.x;   // 512 threads
    hs[t]       = hbuf[((size_t)b*S_)*D_ + t];
    hs[t + 512] = hbuf[((size_t)b*S_)*D_ + t + 512];
    __syncthreads();
    float acc = 0.f;
    for (int k = 0; k < 1024; k++) acc += hs[k] * Wc1[(size_t)k*512 + t];
    acc += bc1[t];
    g_cls[b*512 + t] = fmaxf(acc, 0.f);
}

__global__ void cls2_kernel(const float* __restrict__ Wc2, const float* __restrict__ bc2,
                            float* __restrict__ out) {
    __shared__ float ts[512];
    int b = blockIdx.x, t = threadIdx.x;   // 256 threads
    ts[t]       = g_cls[b*512 + t];
    ts[t + 256] = g_cls[b*512 + t + 256];
    __syncthreads();
    #pragma unroll
    for (int j = 0; j < 4; j++) {
        int o = t + j*256;
        if (o < NLBL_) {
            float acc = 0.f;
            for (int k = 0; k < 512; k++) acc += ts[k] * Wc2[(size_t)k*NLBL_ + o];
            out[b*NLBL_ + o] = acc + bc2[o];
        }
    }
}

// ---------------- host orchestration ------------------------------------------
extern "C" void kernel_launch(void* const* d_in, const int* in_sizes, int n_in,
                              void* d_out, int out_size) {
    const float* x     = (const float*)d_in[0];
    const float* mask  = (const float*)d_in[1];
    const float* pos   = (const float*)d_in[2];
    const float* embln = (const float*)d_in[3];
    const float* Wq = (const float*)d_in[4];
    const float* bq = (const float*)d_in[5];
    const float* Wk = (const float*)d_in[6];
    const float* bk = (const float*)d_in[7];
    const float* Wv = (const float*)d_in[8];
    const float* bv = (const float*)d_in[9];
    const float* Wo = (const float*)d_in[10];
    const float* bo = (const float*)d_in[11];
    const float* ln1 = (const float*)d_in[12];
    const float* W1 = (const float*)d_in[13];
    const float* b1 = (const float*)d_in[14];
    const float* W2 = (const float*)d_in[15];
    const float* b2 = (const float*)d_in[16];
    const float* ln2 = (const float*)d_in[17];
    const float* Wc1 = (const float*)d_in[18];
    const float* bc1 = (const float*)d_in[19];
    const float* Wc2 = (const float*)d_in[20];
    const float* bc2 = (const float*)d_in[21];
    const int*   rnd = (const int*)d_in[22];
    float* out = (float*)d_out;

    float *ph, *pt, *pq, *pk, *pv, *pa, *pf;
    cudaGetSymbolAddress((void**)&ph, g_h);
    cudaGetSymbolAddress((void**)&pt, g_t);
    cudaGetSymbolAddress((void**)&pq, g_q);
    cudaGetSymbolAddress((void**)&pk, g_k);
    cudaGetSymbolAddress((void**)&pv, g_v);
    cudaGetSymbolAddress((void**)&pa, g_attn);
    cudaGetSymbolAddress((void**)&pf, g_ff);

    cudaFuncSetAttribute(attn_inner_kernel,  cudaFuncAttributeMaxDynamicSharedMemorySize, SMEM_INNER);
    cudaFuncSetAttribute(attn_global_kernel, cudaFuncAttributeMaxDynamicSharedMemorySize, SMEM_GLOB);

    // embed + LN
    embed_kernel<<<BS_, 256>>>(x, pos, embln, embln + D_);

    dim3 gD(D_/128, BS_/128);     // N=1024 GEMMs
    dim3 gF(FF_/128, BS_/128);    // N=4096 GEMM

    for (int l = 0; l < L_; l++) {
        const float* lWq = Wq + (size_t)l*D_*D_;
        const float* lWk = Wk + (size_t)l*D_*D_;
        const float* lWv = Wv + (size_t)l*D_*D_;
        const float* lWo = Wo + (size_t)l*D_*D_;
        const float* lW1 = W1 + (size_t)l*D_*FF_;
        const float* lW2 = W2 + (size_t)l*FF_*D_;

        sgemm_kernel<<<gD, 256>>>(ph, lWq, bq + (size_t)l*D_, nullptr, pq, BS_, D_, D_, 0);
        sgemm_kernel<<<gD, 256>>>(ph, lWk, bk + (size_t)l*D_, nullptr, pk, BS_, D_, D_, 0);
        sgemm_kernel<<<gD, 256>>>(ph, lWv, bv + (size_t)l*D_, nullptr, pv, BS_, D_, D_, 0);

        attn_inner_kernel<<<dim3(NI_, H_, B_), 256, SMEM_INNER>>>(mask, rnd);
        attn_global_kernel<<<dim3(4, 2, B_*H_), 256, SMEM_GLOB>>>(mask);

        // t = h + attn@Wo + bo ; LN1 in place
        sgemm_kernel<<<gD, 256>>>(pa, lWo, bo + (size_t)l*D_, ph, pt, BS_, D_, D_, 1);
        ln_kernel<<<BS_, 256>>>(pt, ln1 + (size_t)l*2*D_, ln1 + (size_t)l*2*D_ + D_);

        // ff = gelu(t@W1 + b1) ; h = t + ff@W2 + b2 ; LN2 in place
        sgemm_kernel<<<gF, 256>>>(pt, lW1, b1 + (size_t)l*FF_, nullptr, pf, BS_, FF_, D_, 2);
        sgemm_kernel<<<gD, 256>>>(pf, lW2, b2 + (size_t)l*D_, pt, ph, BS_, D_, FF_, 1);
        ln_kernel<<<BS_, 256>>>(ph, ln2 + (size_t)l*2*D_, ln2 + (size_t)l*2*D_ + D_);
    }

    cls1_kernel<<<B_, 512>>>(ph, Wc1, bc1);
    cls2_kernel<<<B_, 256>>>(Wc2, bc2, out);
}

// round 11
// speedup vs baseline: 1.0012x; 1.0012x over previous
#include <cuda_runtime.h>
#include <math.h>

#define B_  4
#define S_  1920
#define D_  1024
#define H_  8
#define L_  6
#define BLK_ 64
#define NB_ 30
#define NI_ 28
#define R_  3
#define FF_ 4096
#define DH_ 128
#define NLBL_ 1000
#define BS_ (B_*S_)
#define NEGF (-1.0e9f)

// ---------------- scratch (device globals; no allocation allowed) ------------
__device__ float g_h [(size_t)BS_*D_];
__device__ float g_t [(size_t)BS_*D_];
__device__ float g_q [(size_t)BS_*D_];
__device__ float g_k [(size_t)BS_*D_];
__device__ float g_v [(size_t)BS_*D_];
__device__ float g_attn[(size_t)BS_*D_];
__device__ float g_ff[(size_t)BS_*FF_];
__device__ float g_cls[B_*512];

// ---------------- helpers ----------------------------------------------------
__device__ __forceinline__ float gelu_f(float z) {
    // jax.nn.gelu approximate=True (tanh form)
    float z3 = z*z*z;
    return 0.5f*z*(1.0f + tanhf(0.7978845608028654f*(z + 0.044715f*z3)));
}

__device__ __forceinline__ float blockSum256(float v, float* red) {
    #pragma unroll
    for (int o = 16; o; o >>= 1) v += __shfl_xor_sync(0xffffffffu, v, o);
    __syncthreads();
    if ((threadIdx.x & 31) == 0) red[threadIdx.x >> 5] = v;
    __syncthreads();
    if (threadIdx.x == 0) {
        float t = 0.f;
        #pragma unroll
        for (int i = 0; i < 8; i++) t += red[i];
        red[8] = t;
    }
    __syncthreads();
    return red[8];
}

// ---------------- embedding: h = LN(x + pos_emb) ------------------------------
__global__ void embed_kernel(const float* __restrict__ x, const float* __restrict__ pos,
                             const float* __restrict__ gm, const float* __restrict__ bt) {
    __shared__ float red[9];
    int row = blockIdx.x;            // 0..BS_-1
    int s   = row % S_;
    const float* xr = x + (size_t)row*D_;
    const float* pr = pos + (size_t)s*D_;
    int t = threadIdx.x;             // 256 threads
    float v[4];
    #pragma unroll
    for (int j = 0; j < 4; j++) { int c = t + j*256; v[j] = xr[c] + pr[c]; }
    float su = v[0]+v[1]+v[2]+v[3];
    float mean = blockSum256(su, red) * (1.0f/(float)D_);
    float d[4], sq = 0.f;
    #pragma unroll
    for (int j = 0; j < 4; j++) { d[j] = v[j] - mean; sq += d[j]*d[j]; }
    float var = blockSum256(sq, red) * (1.0f/(float)D_);
    float rs = rsqrtf(var + 1e-12f);
    float* hr = g_h + (size_t)row*D_;
    #pragma unroll
    for (int j = 0; j < 4; j++) { int c = t + j*256; hr[c] = d[j]*rs*gm[c] + bt[c]; }
}

// ---------------- layernorm in place -----------------------------------------
__global__ void ln_kernel(float* __restrict__ x,
                          const float* __restrict__ gm, const float* __restrict__ bt) {
    __shared__ float red[9];
    int row = blockIdx.x;
    float* xr = x + (size_t)row*D_;
    int t = threadIdx.x;             // 256
    float v[4];
    #pragma unroll
    for (int j = 0; j < 4; j++) v[j] = xr[t + j*256];
    float su = v[0]+v[1]+v[2]+v[3];
    float mean = blockSum256(su, red) * (1.0f/(float)D_);
    float d[4], sq = 0.f;
    #pragma unroll
    for (int j = 0; j < 4; j++) { d[j] = v[j] - mean; sq += d[j]*d[j]; }
    float var = blockSum256(sq, red) * (1.0f/(float)D_);
    float rs = rsqrtf(var + 1e-12f);
    #pragma unroll
    for (int j = 0; j < 4; j++) { int c = t + j*256; xr[c] = d[j]*rs*gm[c] + bt[c]; }
}

// ---------------- SGEMM: C = A(MxK) @ Bw(KxN) + bias [+res | gelu] -----------
// BM=BN=128, BK=8, 256 threads, 8x8 micro-tile
__global__ __launch_bounds__(256, 2)
void sgemm_kernel(const float* __restrict__ A, const float* __restrict__ Bw,
                  const float* __restrict__ bias, const float* __restrict__ res,
                  float* __restrict__ C, int M, int N, int K, int epi) {
    __shared__ float As[8][132];
    __shared__ float Bs[8][128];
    int bm = blockIdx.y * 128, bn = blockIdx.x * 128;
    int tid = threadIdx.x;
    int arow = tid >> 1, acol = (tid & 1) << 2;
    int brow = tid >> 5, bcol = (tid & 31) << 2;
    int tx = tid & 15, ty = tid >> 4;
    const float* Ap = A + (size_t)(bm + arow)*K + acol;
    const float* Bp = Bw + (size_t)brow*N + bn + bcol;
    float acc[8][8];
    #pragma unroll
    for (int i = 0; i < 8; i++)
        #pragma unroll
        for (int j = 0; j < 8; j++) acc[i][j] = 0.f;
    int nk = K >> 3;
    for (int kt = 0; kt < nk; kt++) {
        float4 a4 = *(const float4*)Ap;
        float4 b4 = *(const float4*)Bp;
        As[acol+0][arow] = a4.x; As[acol+1][arow] = a4.y;
        As[acol+2][arow] = a4.z; As[acol+3][arow] = a4.w;
        *(float4*)&Bs[brow][bcol] = b4;
        __syncthreads();
        #pragma unroll
        for (int kk = 0; kk < 8; kk++) {
            float fa[8], fb[8];
            *(float4*)&fa[0] = *(const float4*)&As[kk][ty*8];
            *(float4*)&fa[4] = *(const float4*)&As[kk][ty*8+4];
            *(float4*)&fb[0] = *(const float4*)&Bs[kk][tx*8];
            *(float4*)&fb[4] = *(const float4*)&Bs[kk][tx*8+4];
            #pragma unroll
            for (int i = 0; i < 8; i++)
                #pragma unroll
                for (int j = 0; j < 8; j++)
                    acc[i][j] += fa[i]*fb[j];
        }
        __syncthreads();
        Ap += 8; Bp += (size_t)8*N;
    }
    #pragma unroll
    for (int i = 0; i < 8; i++) {
        int r = bm + ty*8 + i;
        size_t off = (size_t)r*N + bn + tx*8;
        #pragma unroll
        for (int j = 0; j < 8; j++) {
            int cidx = bn + tx*8 + j;
            float vv = acc[i][j] + bias[cidx];
            if (epi == 1)      vv += res[off + j];
            else if (epi == 2) vv = gelu_f(vv);
            C[off + j] = vv;
        }
    }
}

// ---------------- inner-block BigBird attention --------------------------------
// grid (NI_, H_, B_), 256 threads. Dynamic smem:
//   Qs 64x129 | KV 64x129 | Sc 64x516   = 49536 floats = 198144 B
#define SMEM_INNER (49536*4)
__global__ void attn_inner_kernel(const float* __restrict__ mask, const int* __restrict__ rnd) {
    extern __shared__ float sm[];
    float* Qs = sm;
    float* KV = sm + 64*129;
    float* Sc = sm + 2*64*129;
    __shared__ int   kblk[8];
    __shared__ float keepm[8];

    const int i = blockIdx.x, h = blockIdx.y, b = blockIdx.z;
    const int tid = threadIdx.x;
    const int tok0 = (i + 1) * BLK_;
    const float scale = 0.08838834764831845f;   // 1/sqrt(128)

    if (tid == 0) {
        int idx8[8];
        idx8[0] = 0; idx8[1] = NB_-1; idx8[2] = i; idx8[3] = i+1; idx8[4] = i+2;
        idx8[5] = rnd[(h*NI_ + i)*R_ + 0];
        idx8[6] = rnd[(h*NI_ + i)*R_ + 1];
        idx8[7] = rnd[(h*NI_ + i)*R_ + 2];
        #pragma unroll
        for (int j = 0; j < 8; j++) {
            float kp = 1.f;
            for (int j2 = 0; j2 < j; j2++) if (idx8[j2] == idx8[j]) kp = 0.f;
            kblk[j] = idx8[j]; keepm[j] = kp;
        }
    }
    // load Q (scaled)
    for (int t = tid; t < 64*32; t += 256) {
        int r = t >> 5, c = (t & 31) << 2;
        float4 v4 = *(const float4*)(g_q + ((size_t)(b*S_ + tok0 + r))*D_ + h*DH_ + c);
        float* dst = Qs + r*129 + c;
        dst[0] = v4.x*scale; dst[1] = v4.y*scale; dst[2] = v4.z*scale; dst[3] = v4.w*scale;
    }
    __syncthreads();

    const int ty = tid >> 4, tx = tid & 15;

    // ---- scores: 8 key blocks of 64 keys
    for (int jb = 0; jb < 8; jb++) {
        int kt0 = kblk[jb] * BLK_;
        for (int t = tid; t < 64*32; t += 256) {
            int r = t >> 5, c = (t & 31) << 2;
            float4 v4 = *(const float4*)(g_k + ((size_t)(b*S_ + kt0 + r))*D_ + h*DH_ + c);
            float* dst = KV + r*129 + c;
            dst[0] = v4.x; dst[1] = v4.y; dst[2] = v4.z; dst[3] = v4.w;
        }
        __syncthreads();
        float acc[4][4];
        #pragma unroll
        for (int a = 0; a < 4; a++)
            #pragma unroll
            for (int c2 = 0; c2 < 4; c2++) acc[a][c2] = 0.f;
        #pragma unroll 4
        for (int d = 0; d < 128; d++) {
            float fa[4], fb[4];
            #pragma unroll
            for (int u = 0; u < 4; u++) fa[u] = Qs[(ty*4+u)*129 + d];
            #pragma unroll
            for (int u = 0; u < 4; u++) fb[u] = KV[(tx*4+u)*129 + d];
            #pragma unroll
            for (int a = 0; a < 4; a++)
                #pragma unroll
                for (int c2 = 0; c2 < 4; c2++) acc[a][c2] += fa[a]*fb[c2];
        }
        float km = keepm[jb];
        #pragma unroll
        for (int c2 = 0; c2 < 4; c2++) {
            int kk = tx*4 + c2;
            float mg = km * mask[b*S_ + kt0 + kk];
            #pragma unroll
            for (int a = 0; a < 4; a++)
                Sc[(ty*4+a)*516 + jb*64 + kk] = (mg > 0.f) ? acc[a][c2] : NEGF;
        }
        __syncthreads();
    }

    // ---- softmax per row over 512 keys (4 threads per row)
    {
        int row = tid >> 2, l4 = tid & 3;
        float* Sr = Sc + row*516;
        float mx = -3.0e38f;
        for (int kk = l4; kk < 512; kk += 4) mx = fmaxf(mx, Sr[kk]);
        mx = fmaxf(mx, __shfl_xor_sync(0xffffffffu, mx, 1));
        mx = fmaxf(mx, __shfl_xor_sync(0xffffffffu, mx, 2));
        float su = 0.f;
        for (int kk = l4; kk < 512; kk += 4) {
            float p = __expf(Sr[kk] - mx);
            Sr[kk] = p; su += p;
        }
        su += __shfl_xor_sync(0xffffffffu, su, 1);
        su += __shfl_xor_sync(0xffffffffu, su, 2);
        float inv = 1.0f / su;
        for (int kk = l4; kk < 512; kk += 4) Sr[kk] *= inv;
    }
    __syncthreads();

    // ---- O = P @ V : 64x128, micro 4 rows x 8 cols
    float oacc[4][8];
    #pragma unroll
    for (int a = 0; a < 4; a++)
        #pragma unroll
        for (int c2 = 0; c2 < 8; c2++) oacc[a][c2] = 0.f;
    for (int jb = 0; jb < 8; jb++) {
        int kt0 = kblk[jb] * BLK_;
        for (int t = tid; t < 64*32; t += 256) {
            int r = t >> 5, c = (t & 31) << 2;
            float4 v4 = *(const float4*)(g_v + ((size_t)(b*S_ + kt0 + r))*D_ + h*DH_ + c);
            float* dst = KV + r*129 + c;
            dst[0] = v4.x; dst[1] = v4.y; dst[2] = v4.z; dst[3] = v4.w;
        }
        __syncthreads();
        #pragma unroll 2
        for (int kk = 0; kk < 64; kk++) {
            float pa[4], vb[8];
            #pragma unroll
            for (int u = 0; u < 4; u++) pa[u] = Sc[(ty*4+u)*516 + jb*64 + kk];
            #pragma unroll
            for (int u = 0; u < 8; u++) vb[u] = KV[kk*129 + tx*8 + u];
            #pragma unroll
            for (int a = 0; a < 4; a++)
                #pragma unroll
                for (int c2 = 0; c2 < 8; c2++) oacc[a][c2] += pa[a]*vb[c2];
        }
        __syncthreads();
    }
    #pragma unroll
    for (int a = 0; a < 4; a++) {
        int tok = tok0 + ty*4 + a;
        float* dst = g_attn + ((size_t)(b*S_ + tok))*D_ + h*DH_ + tx*8;
        #pragma unroll
        for (int c2 = 0; c2 < 8; c2++) dst[c2] = oacc[a][c2];
    }
}

// ---------------- global-block attention (flash over 30 chunks) ---------------
// grid (4 qsub, 2 g, B_*H_), 256 threads.
// smem: Qs 16x129 | Ks 64x129 | Vs 64x129 | Ss 16x68 | m/l/corr 16 each
#define SMEM_GLOB ((16*129 + 2*64*129 + 16*68 + 48)*4)
__global__ void attn_global_kernel(const float* __restrict__ mask) {
    extern __shared__ float sm[];
    float* Qs = sm;
    float* Ks = Qs + 16*129;
    float* Vs = Ks + 64*129;
    float* Ss = Vs + 64*129;
    float* mrow = Ss + 16*68;
    float* lrow = mrow + 16;
    float* crow = lrow + 16;

    const int qs = blockIdx.x;
    const int g  = blockIdx.y;
    const int b  = blockIdx.z >> 3, h = blockIdx.z & 7;
    const int tid = threadIdx.x;
    const int tok0 = (g == 0 ? 0 : (NB_-1)*BLK_) + qs*16;
    const float scale = 0.08838834764831845f;

    for (int t = tid; t < 16*32; t += 256) {
        int r = t >> 5, c = (t & 31) << 2;
        float4 v4 = *(const float4*)(g_q + ((size_t)(b*S_ + tok0 + r))*D_ + h*DH_ + c);
        float* dst = Qs + r*129 + c;
        dst[0] = v4.x*scale; dst[1] = v4.y*scale; dst[2] = v4.z*scale; dst[3] = v4.w*scale;
    }
    if (tid < 16) { mrow[tid] = -3.0e38f; lrow[tid] = 0.f; }
    __syncthreads();

    const int row = tid >> 4, tx = tid & 15;
    float oacc[8];
    #pragma unroll
    for (int u = 0; u < 8; u++) oacc[u] = 0.f;

    for (int cb = 0; cb < NB_; cb++) {
        int kt0 = cb * BLK_;
        for (int t = tid; t < 64*32; t += 256) {
            int r = t >> 5, c = (t & 31) << 2;
            size_t gi = ((size_t)(b*S_ + kt0 + r))*D_ + h*DH_ + c;
            float4 k4 = *(const float4*)(g_k + gi);
            float4 v4 = *(const float4*)(g_v + gi);
            float* dk = Ks + r*129 + c;
            float* dv = Vs + r*129 + c;
            dk[0]=k4.x; dk[1]=k4.y; dk[2]=k4.z; dk[3]=k4.w;
            dv[0]=v4.x; dv[1]=v4.y; dv[2]=v4.z; dv[3]=v4.w;
        }
        __syncthreads();
        // scores: each thread 1 row x 4 keys
        float sc4[4] = {0.f, 0.f, 0.f, 0.f};
        #pragma unroll 4
        for (int d = 0; d < 128; d++) {
            float qa = Qs[row*129 + d];
            #pragma unroll
            for (int u = 0; u < 4; u++) sc4[u] += qa * Ks[(tx*4+u)*129 + d];
        }
        #pragma unroll
        for (int u = 0; u < 4; u++) {
            int kk = tx*4 + u;
            float mg = mask[b*S_ + kt0 + kk];
            Ss[row*68 + kk] = (mg > 0.f) ? sc4[u] : NEGF;
        }
        __syncthreads();
        if (tid < 16) {
            float* Sr = Ss + tid*68;
            float cmax = -3.0e38f;
            for (int kk = 0; kk < 64; kk++) cmax = fmaxf(cmax, Sr[kk]);
            float m0 = mrow[tid];
            float nm = fmaxf(m0, cmax);
            float cr = __expf(m0 - nm);
            float sn = 0.f;
            for (int kk = 0; kk < 64; kk++) {
                float p = __expf(Sr[kk] - nm);
                Sr[kk] = p; sn += p;
            }
            lrow[tid] = lrow[tid]*cr + sn;
            mrow[tid] = nm;
            crow[tid] = cr;
        }
        __syncthreads();
        float cr = crow[row];
        #pragma unroll
        for (int u = 0; u < 8; u++) oacc[u] *= cr;
        #pragma unroll 2
        for (int kk = 0; kk < 64; kk++) {
            float p = Ss[row*68 + kk];
            #pragma unroll
            for (int u = 0; u < 8; u++) oacc[u] += p * Vs[kk*129 + tx*8 + u];
        }
        __syncthreads();
    }
    float inv = 1.0f / lrow[row];
    float* dst = g_attn + ((size_t)(b*S_ + tok0 + row))*D_ + h*DH_ + tx*8;
    #pragma unroll
    for (int u = 0; u < 8; u++) dst[u] = oacc[u]*inv;
}

// ---------------- classifier ---------------------------------------------------
__global__ void cls1_kernel(const float* __restrict__ hbuf, const float* __restrict__ Wc1,
                            const float* __restrict__ bc1) {
    __shared__ float hs[1024];
    int b = blockIdx.x, t = threadIdx.x;   // 512 threads
    hs[t]       = hbuf[((size_t)b*S_)*D_ + t];
    hs[t + 512] = hbuf[((size_t)b*S_)*D_ + t + 512];
    __syncthreads();
    float acc = 0.f;
    for (int k = 0; k < 1024; k++) acc += hs[k] * Wc1[(size_t)k*512 + t];
    acc += bc1[t];
    g_cls[b*512 + t] = fmaxf(acc, 0.f);
}

__global__ void cls2_kernel(const float* __restrict__ Wc2, const float* __restrict__ bc2,
                            float* __restrict__ out) {
    __shared__ float ts[512];
    int b = blockIdx.x, t = threadIdx.x;   // 256 threads
    ts[t]       = g_cls[b*512 + t];
    ts[t + 256] = g_cls[b*512 + t + 256];
    __syncthreads();
    #pragma unroll
    for (int j = 0; j < 4; j++) {
        int o = t + j*256;
        if (o < NLBL_) {
            float acc = 0.f;
            for (int k = 0; k < 512; k++) acc += ts[k] * Wc2[(size_t)k*NLBL_ + o];
            out[b*NLBL_ + o] = acc + bc2[o];
        }
    }
}

// ---------------- host orchestration ------------------------------------------
extern "C" void kernel_launch(void* const* d_in, const int* in_sizes, int n_in,
                              void* d_out, int out_size) {
    const float* x     = (const float*)d_in[0];
    const float* mask  = (const float*)d_in[1];
    const float* pos   = (const float*)d_in[2];
    const float* embln = (const float*)d_in[3];
    const float* Wq = (const float*)d_in[4];
    const float* bq = (const float*)d_in[5];
    const float* Wk = (const float*)d_in[6];
    const float* bk = (const float*)d_in[7];
    const float* Wv = (const float*)d_in[8];
    const float* bv = (const float*)d_in[9];
    const float* Wo = (const float*)d_in[10];
    const float* bo = (const float*)d_in[11];
    const float* ln1 = (const float*)d_in[12];
    const float* W1 = (const float*)d_in[13];
    const float* b1 = (const float*)d_in[14];
    const float* W2 = (const float*)d_in[15];
    const float* b2 = (const float*)d_in[16];
    const float* ln2 = (const float*)d_in[17];
    const float* Wc1 = (const float*)d_in[18];
    const float* bc1 = (const float*)d_in[19];
    const float* Wc2 = (const float*)d_in[20];
    const float* bc2 = (const float*)d_in[21];
    const int*   rnd = (const int*)d_in[22];
    float* out = (float*)d_out;

    float *ph, *pt, *pq, *pk, *pv, *pa, *pf;
    cudaGetSymbolAddress((void**)&ph, g_h);
    cudaGetSymbolAddress((void**)&pt, g_t);
    cudaGetSymbolAddress((void**)&pq, g_q);
    cudaGetSymbolAddress((void**)&pk, g_k);
    cudaGetSymbolAddress((void**)&pv, g_v);
    cudaGetSymbolAddress((void**)&pa, g_attn);
    cudaGetSymbolAddress((void**)&pf, g_ff);

    cudaFuncSetAttribute(attn_inner_kernel,  cudaFuncAttributeMaxDynamicSharedMemorySize, SMEM_INNER);
    cudaFuncSetAttribute(attn_global_kernel, cudaFuncAttributeMaxDynamicSharedMemorySize, SMEM_GLOB);

    // embed + LN
    embed_kernel<<<BS_, 256>>>(x, pos, embln, embln + D_);

    dim3 gD(D_/128, BS_/128);     // N=1024 GEMMs
    dim3 gF(FF_/128, BS_/128);    // N=4096 GEMM

    for (int l = 0; l < L_; l++) {
        const float* lWq = Wq + (size_t)l*D_*D_;
        const float* lWk = Wk + (size_t)l*D_*D_;
        const float* lWv = Wv + (size_t)l*D_*D_;
        const float* lWo = Wo + (size_t)l*D_*D_;
        const float* lW1 = W1 + (size_t)l*D_*FF_;
        const float* lW2 = W2 + (size_t)l*FF_*D_;

        sgemm_kernel<<<gD, 256>>>(ph, lWq, bq + (size_t)l*D_, nullptr, pq, BS_, D_, D_, 0);
        sgemm_kernel<<<gD, 256>>>(ph, lWk, bk + (size_t)l*D_, nullptr, pk, BS_, D_, D_, 0);
        sgemm_kernel<<<gD, 256>>>(ph, lWv, bv + (size_t)l*D_, nullptr, pv, BS_, D_, D_, 0);

        attn_inner_kernel<<<dim3(NI_, H_, B_), 256, SMEM_INNER>>>(mask, rnd);
        attn_global_kernel<<<dim3(4, 2, B_*H_), 256, SMEM_GLOB>>>(mask);

        // t = h + attn@Wo + bo ; LN1 in place
        sgemm_kernel<<<gD, 256>>>(pa, lWo, bo + (size_t)l*D_, ph, pt, BS_, D_, D_, 1);
        ln_kernel<<<BS_, 256>>>(pt, ln1 + (size_t)l*2*D_, ln1 + (size_t)l*2*D_ + D_);

        // ff = gelu(t@W1 + b1) ; h = t + ff@W2 + b2 ; LN2 in place
        sgemm_kernel<<<gF, 256>>>(pt, lW1, b1 + (size_t)l*FF_, nullptr, pf, BS_, FF_, D_, 2);
        sgemm_kernel<<<gD, 256>>>(pf, lW2, b2 + (size_t)l*D_, pt, ph, BS_, D_, FF_, 1);
        ln_kernel<<<BS_, 256>>>(ph, ln2 + (size_t)l*2*D_, ln2 + (size_t)l*2*D_ + D_);
    }

    cls1_kernel<<<B_, 512>>>(ph, Wc1, bc1);
    cls2_kernel<<<B_, 256>>>(Wc2, bc2, out);
}

// round 12
// speedup vs baseline: 1.0029x; 1.0017x over previous
#include <cuda_runtime.h>
#include <math.h>

#define B_  4
#define S_  1920
#define D_  1024
#define H_  8
#define L_  6
#define BLK_ 64
#define NB_ 30
#define NI_ 28
#define R_  3
#define FF_ 4096
#define DH_ 128
#define NLBL_ 1000
#define BS_ (B_*S_)
#define NEGF (-1.0e9f)

// ---------------- scratch (device globals; no allocation allowed) ------------
__device__ float g_h [(size_t)BS_*D_];
__device__ float g_t [(size_t)BS_*D_];
__device__ float g_q [(size_t)BS_*D_];
__device__ float g_k [(size_t)BS_*D_];
__device__ float g_v [(size_t)BS_*D_];
__device__ float g_attn[(size_t)BS_*D_];
__device__ float g_ff[(size_t)BS_*FF_];
__device__ float g_cls[B_*512];

// ---------------- helpers ----------------------------------------------------
__device__ __forceinline__ float gelu_f(float z) {
    // jax.nn.gelu approximate=True (tanh form)
    float z3 = z*z*z;
    return 0.5f*z*(1.0f + tanhf(0.7978845608028654f*(z + 0.044715f*z3)));
}

__device__ __forceinline__ float blockSum256(float v, float* red) {
    #pragma unroll
    for (int o = 16; o; o >>= 1) v += __shfl_xor_sync(0xffffffffu, v, o);
    __syncthreads();
    if ((threadIdx.x & 31) == 0) red[threadIdx.x >> 5] = v;
    __syncthreads();
    if (threadIdx.x == 0) {
        float t = 0.f;
        #pragma unroll
        for (int i = 0; i < 8; i++) t += red[i];
        red[8] = t;
    }
    __syncthreads();
    return red[8];
}

// ---------------- embedding: h = LN(x + pos_emb) ------------------------------
__global__ void embed_kernel(const float* __restrict__ x, const float* __restrict__ pos,
                             const float* __restrict__ gm, const float* __restrict__ bt) {
    __shared__ float red[9];
    int row = blockIdx.x;            // 0..BS_-1
    int s   = row % S_;
    const float* xr = x + (size_t)row*D_;
    const float* pr = pos + (size_t)s*D_;
    int t = threadIdx.x;             // 256 threads
    float v[4];
    #pragma unroll
    for (int j = 0; j < 4; j++) { int c = t + j*256; v[j] = xr[c] + pr[c]; }
    float su = v[0]+v[1]+v[2]+v[3];
    float mean = blockSum256(su, red) * (1.0f/(float)D_);
    float d[4], sq = 0.f;
    #pragma unroll
    for (int j = 0; j < 4; j++) { d[j] = v[j] - mean; sq += d[j]*d[j]; }
    float var = blockSum256(sq, red) * (1.0f/(float)D_);
    float rs = rsqrtf(var + 1e-12f);
    float* hr = g_h + (size_t)row*D_;
    #pragma unroll
    for (int j = 0; j < 4; j++) { int c = t + j*256; hr[c] = d[j]*rs*gm[c] + bt[c]; }
}

// ---------------- layernorm in place -----------------------------------------
__global__ void ln_kernel(float* __restrict__ x,
                          const float* __restrict__ gm, const float* __restrict__ bt) {
    __shared__ float red[9];
    int row = blockIdx.x;
    float* xr = x + (size_t)row*D_;
    int t = threadIdx.x;             // 256
    float v[4];
    #pragma unroll
    for (int j = 0; j < 4; j++) v[j] = xr[t + j*256];
    float su = v[0]+v[1]+v[2]+v[3];
    float mean = blockSum256(su, red) * (1.0f/(float)D_);
    float d[4], sq = 0.f;
    #pragma unroll
    for (int j = 0; j < 4; j++) { d[j] = v[j] - mean; sq += d[j]*d[j]; }
    float var = blockSum256(sq, red) * (1.0f/(float)D_);
    float rs = rsqrtf(var + 1e-12f);
    #pragma unroll
    for (int j = 0; j < 4; j++) { int c = t + j*256; xr[c] = d[j]*rs*gm[c] + bt[c]; }
}

// ---------------- SGEMM: C = A(MxK) @ Bw(KxN) + bias [+res | gelu] -----------
// BM=BN=128, BK=8, 256 threads, 8x8 micro-tile
__global__ __launch_bounds__(256, 2)
void sgemm_kernel(const float* __restrict__ A, const float* __restrict__ Bw,
                  const float* __restrict__ bias, const float* __restrict__ res,
                  float* __restrict__ C, int M, int N, int K, int epi) {
    __shared__ float As[8][132];
    __shared__ float Bs[8][128];
    int bm = blockIdx.y * 128, bn = blockIdx.x * 128;
    int tid = threadIdx.x;
    int arow = tid >> 1, acol = (tid & 1) << 2;
    int brow = tid >> 5, bcol = (tid & 31) << 2;
    int tx = tid & 15, ty = tid >> 4;
    const float* Ap = A + (size_t)(bm + arow)*K + acol;
    const float* Bp = Bw + (size_t)brow*N + bn + bcol;
    float acc[8][8];
    #pragma unroll
    for (int i = 0; i < 8; i++)
        #pragma unroll
        for (int j = 0; j < 8; j++) acc[i][j] = 0.f;
    int nk = K >> 3;
    for (int kt = 0; kt < nk; kt++) {
        float4 a4 = *(const float4*)Ap;
        float4 b4 = *(const float4*)Bp;
        As[acol+0][arow] = a4.x; As[acol+1][arow] = a4.y;
        As[acol+2][arow] = a4.z; As[acol+3][arow] = a4.w;
        *(float4*)&Bs[brow][bcol] = b4;
        __syncthreads();
        #pragma unroll
        for (int kk = 0; kk < 8; kk++) {
            float fa[8], fb[8];
            *(float4*)&fa[0] = *(const float4*)&As[kk][ty*8];
            *(float4*)&fa[4] = *(const float4*)&As[kk][ty*8+4];
            *(float4*)&fb[0] = *(const float4*)&Bs[kk][tx*8];
            *(float4*)&fb[4] = *(const float4*)&Bs[kk][tx*8+4];
            #pragma unroll
            for (int i = 0; i < 8; i++)
                #pragma unroll
                for (int j = 0; j < 8; j++)
                    acc[i][j] += fa[i]*fb[j];
        }
        __syncthreads();
        Ap += 8; Bp += (size_t)8*N;
    }
    #pragma unroll
    for (int i = 0; i < 8; i++) {
        int r = bm + ty*8 + i;
        size_t off = (size_t)r*N + bn + tx*8;
        #pragma unroll
        for (int j = 0; j < 8; j++) {
            int cidx = bn + tx*8 + j;
            float vv = acc[i][j] + bias[cidx];
            if (epi == 1)      vv += res[off + j];
            else if (epi == 2) vv = gelu_f(vv);
            C[off + j] = vv;
        }
    }
}

// ---------------- inner-block BigBird attention --------------------------------
// grid (NI_, H_, B_), 256 threads. Dynamic smem:
//   Qs 64x129 | KV 64x129 | Sc 64x516   = 49536 floats = 198144 B
#define SMEM_INNER (49536*4)
__global__ void attn_inner_kernel(const float* __restrict__ mask, const int* __restrict__ rnd) {
    extern __shared__ float sm[];
    float* Qs = sm;
    float* KV = sm + 64*129;
    float* Sc = sm + 2*64*129;
    __shared__ int   kblk[8];
    __shared__ float keepm[8];

    const int i = blockIdx.x, h = blockIdx.y, b = blockIdx.z;
    const int tid = threadIdx.x;
    const int tok0 = (i + 1) * BLK_;
    const float scale = 0.08838834764831845f;   // 1/sqrt(128)

    if (tid == 0) {
        int idx8[8];
        idx8[0] = 0; idx8[1] = NB_-1; idx8[2] = i; idx8[3] = i+1; idx8[4] = i+2;
        idx8[5] = rnd[(h*NI_ + i)*R_ + 0];
        idx8[6] = rnd[(h*NI_ + i)*R_ + 1];
        idx8[7] = rnd[(h*NI_ + i)*R_ + 2];
        #pragma unroll
        for (int j = 0; j < 8; j++) {
            float kp = 1.f;
            for (int j2 = 0; j2 < j; j2++) if (idx8[j2] == idx8[j]) kp = 0.f;
            kblk[j] = idx8[j]; keepm[j] = kp;
        }
    }
    // load Q (scaled)
    for (int t = tid; t < 64*32; t += 256) {
        int r = t >> 5, c = (t & 31) << 2;
        float4 v4 = *(const float4*)(g_q + ((size_t)(b*S_ + tok0 + r))*D_ + h*DH_ + c);
        float* dst = Qs + r*129 + c;
        dst[0] = v4.x*scale; dst[1] = v4.y*scale; dst[2] = v4.z*scale; dst[3] = v4.w*scale;
    }
    __syncthreads();

    const int ty = tid >> 4, tx = tid & 15;

    // ---- scores: 8 key blocks of 64 keys
    for (int jb = 0; jb < 8; jb++) {
        int kt0 = kblk[jb] * BLK_;
        for (int t = tid; t < 64*32; t += 256) {
            int r = t >> 5, c = (t & 31) << 2;
            float4 v4 = *(const float4*)(g_k + ((size_t)(b*S_ + kt0 + r))*D_ + h*DH_ + c);
            float* dst = KV + r*129 + c;
            dst[0] = v4.x; dst[1] = v4.y; dst[2] = v4.z; dst[3] = v4.w;
        }
        __syncthreads();
        float acc[4][4];
        #pragma unroll
        for (int a = 0; a < 4; a++)
            #pragma unroll
            for (int c2 = 0; c2 < 4; c2++) acc[a][c2] = 0.f;
        #pragma unroll 4
        for (int d = 0; d < 128; d++) {
            float fa[4], fb[4];
            #pragma unroll
            for (int u = 0; u < 4; u++) fa[u] = Qs[(ty*4+u)*129 + d];
            #pragma unroll
            for (int u = 0; u < 4; u++) fb[u] = KV[(tx*4+u)*129 + d];
            #pragma unroll
            for (int a = 0; a < 4; a++)
                #pragma unroll
                for (int c2 = 0; c2 < 4; c2++) acc[a][c2] += fa[a]*fb[c2];
        }
        float km = keepm[jb];
        #pragma unroll
        for (int c2 = 0; c2 < 4; c2++) {
            int kk = tx*4 + c2;
            float mg = km * mask[b*S_ + kt0 + kk];
            #pragma unroll
            for (int a = 0; a < 4; a++)
                Sc[(ty*4+a)*516 + jb*64 + kk] = (mg > 0.f) ? acc[a][c2] : NEGF;
        }
        __syncthreads();
    }

    // ---- softmax per row over 512 keys (4 threads per row)
    {
        int row = tid >> 2, l4 = tid & 3;
        float* Sr = Sc + row*516;
        float mx = -3.0e38f;
        for (int kk = l4; kk < 512; kk += 4) mx = fmaxf(mx, Sr[kk]);
        mx = fmaxf(mx, __shfl_xor_sync(0xffffffffu, mx, 1));
        mx = fmaxf(mx, __shfl_xor_sync(0xffffffffu, mx, 2));
        float su = 0.f;
        for (int kk = l4; kk < 512; kk += 4) {
            float p = __expf(Sr[kk] - mx);
            Sr[kk] = p; su += p;
        }
        su += __shfl_xor_sync(0xffffffffu, su, 1);
        su += __shfl_xor_sync(0xffffffffu, su, 2);
        float inv = 1.0f / su;
        for (int kk = l4; kk < 512; kk += 4) Sr[kk] *= inv;
    }
    __syncthreads();

    // ---- O = P @ V : 64x128, micro 4 rows x 8 cols
    float oacc[4][8];
    #pragma unroll
    for (int a = 0; a < 4; a++)
        #pragma unroll
        for (int c2 = 0; c2 < 8; c2++) oacc[a][c2] = 0.f;
    for (int jb = 0; jb < 8; jb++) {
        int kt0 = kblk[jb] * BLK_;
        for (int t = tid; t < 64*32; t += 256) {
            int r = t >> 5, c = (t & 31) << 2;
            float4 v4 = *(const float4*)(g_v + ((size_t)(b*S_ + kt0 + r))*D_ + h*DH_ + c);
            float* dst = KV + r*129 + c;
            dst[0] = v4.x; dst[1] = v4.y; dst[2] = v4.z; dst[3] = v4.w;
        }
        __syncthreads();
        #pragma unroll 2
        for (int kk = 0; kk < 64; kk++) {
            float pa[4], vb[8];
            #pragma unroll
            for (int u = 0; u < 4; u++) pa[u] = Sc[(ty*4+u)*516 + jb*64 + kk];
            #pragma unroll
            for (int u = 0; u < 8; u++) vb[u] = KV[kk*129 + tx*8 + u];
            #pragma unroll
            for (int a = 0; a < 4; a++)
                #pragma unroll
                for (int c2 = 0; c2 < 8; c2++) oacc[a][c2] += pa[a]*vb[c2];
        }
        __syncthreads();
    }
    #pragma unroll
    for (int a = 0; a < 4; a++) {
        int tok = tok0 + ty*4 + a;
        float* dst = g_attn + ((size_t)(b*S_ + tok))*D_ + h*DH_ + tx*8;
        #pragma unroll
        for (int c2 = 0; c2 < 8; c2++) dst[c2] = oacc[a][c2];
    }
}

// ---------------- global-block attention (flash over 30 chunks) ---------------
// grid (4 qsub, 2 g, B_*H_), 256 threads.
// smem: Qs 16x129 | Ks 64x129 | Vs 64x129 | Ss 16x68 | m/l/corr 16 each
#define SMEM_GLOB ((16*129 + 2*64*129 + 16*68 + 48)*4)
__global__ void attn_global_kernel(const float* __restrict__ mask) {
    extern __shared__ float sm[];
    float* Qs = sm;
    float* Ks = Qs + 16*129;
    float* Vs = Ks + 64*129;
    float* Ss = Vs + 64*129;
    float* mrow = Ss + 16*68;
    float* lrow = mrow + 16;
    float* crow = lrow + 16;

    const int qs = blockIdx.x;
    const int g  = blockIdx.y;
    const int b  = blockIdx.z >> 3, h = blockIdx.z & 7;
    const int tid = threadIdx.x;
    const int tok0 = (g == 0 ? 0 : (NB_-1)*BLK_) + qs*16;
    const float scale = 0.08838834764831845f;

    for (int t = tid; t < 16*32; t += 256) {
        int r = t >> 5, c = (t & 31) << 2;
        float4 v4 = *(const float4*)(g_q + ((size_t)(b*S_ + tok0 + r))*D_ + h*DH_ + c);
        float* dst = Qs + r*129 + c;
        dst[0] = v4.x*scale; dst[1] = v4.y*scale; dst[2] = v4.z*scale; dst[3] = v4.w*scale;
    }
    if (tid < 16) { mrow[tid] = -3.0e38f; lrow[tid] = 0.f; }
    __syncthreads();

    const int row = tid >> 4, tx = tid & 15;
    float oacc[8];
    #pragma unroll
    for (int u = 0; u < 8; u++) oacc[u] = 0.f;

    for (int cb = 0; cb < NB_; cb++) {
        int kt0 = cb * BLK_;
        for (int t = tid; t < 64*32; t += 256) {
            int r = t >> 5, c = (t & 31) << 2;
            size_t gi = ((size_t)(b*S_ + kt0 + r))*D_ + h*DH_ + c;
            float4 k4 = *(const float4*)(g_k + gi);
            float4 v4 = *(const float4*)(g_v + gi);
            float* dk = Ks + r*129 + c;
            float* dv = Vs + r*129 + c;
            dk[0]=k4.x; dk[1]=k4.y; dk[2]=k4.z; dk[3]=k4.w;
            dv[0]=v4.x; dv[1]=v4.y; dv[2]=v4.z; dv[3]=v4.w;
        }
        __syncthreads();
        // scores: each thread 1 row x 4 keys
        float sc4[4] = {0.f, 0.f, 0.f, 0.f};
        #pragma unroll 4
        for (int d = 0; d < 128; d++) {
            float qa = Qs[row*129 + d];
            #pragma unroll
            for (int u = 0; u < 4; u++) sc4[u] += qa * Ks[(tx*4+u)*129 + d];
        }
        #pragma unroll
        for (int u = 0; u < 4; u++) {
            int kk = tx*4 + u;
            float mg = mask[b*S_ + kt0 + kk];
            Ss[row*68 + kk] = (mg > 0.f) ? sc4[u] : NEGF;
        }
        __syncthreads();
        if (tid < 16) {
            float* Sr = Ss + tid*68;
            float cmax = -3.0e38f;
            for (int kk = 0; kk < 64; kk++) cmax = fmaxf(cmax, Sr[kk]);
            float m0 = mrow[tid];
            float nm = fmaxf(m0, cmax);
            float cr = __expf(m0 - nm);
            float sn = 0.f;
            for (int kk = 0; kk < 64; kk++) {
                float p = __expf(Sr[kk] - nm);
                Sr[kk] = p; sn += p;
            }
            lrow[tid] = lrow[tid]*cr + sn;
            mrow[tid] = nm;
            crow[tid] = cr;
        }
        __syncthreads();
        float cr = crow[row];
        #pragma unroll
        for (int u = 0; u < 8; u++) oacc[u] *= cr;
        #pragma unroll 2
        for (int kk = 0; kk < 64; kk++) {
            float p = Ss[row*68 + kk];
            #pragma unroll
            for (int u = 0; u < 8; u++) oacc[u] += p * Vs[kk*129 + tx*8 + u];
        }
        __syncthreads();
    }
    float inv = 1.0f / lrow[row];
    float* dst = g_attn + ((size_t)(b*S_ + tok0 + row))*D_ + h*DH_ + tx*8;
    #pragma unroll
    for (int u = 0; u < 8; u++) dst[u] = oacc[u]*inv;
}

// ---------------- classifier ---------------------------------------------------
__global__ void cls1_kernel(const float* __restrict__ hbuf, const float* __restrict__ Wc1,
                            const float* __restrict__ bc1) {
    __shared__ float hs[1024];
    int b = blockIdx.x, t = threadIdx.x;   // 512 threads
    hs[t]       = hbuf[((size_t)b*S_)*D_ + t];
    hs[t + 512] = hbuf[((size_t)b*S_)*D_ + t + 512];
    __syncthreads();
    float acc = 0.f;
    for (int k = 0; k < 1024; k++) acc += hs[k] * Wc1[(size_t)k*512 + t];
    acc += bc1[t];
    g_cls[b*512 + t] = fmaxf(acc, 0.f);
}

__global__ void cls2_kernel(const float* __restrict__ Wc2, const float* __restrict__ bc2,
                            float* __restrict__ out) {
    __shared__ float ts[512];
    int b = blockIdx.x, t = threadIdx.x;   // 256 threads
    ts[t]       = g_cls[b*512 + t];
    ts[t + 256] = g_cls[b*512 + t + 256];
    __syncthreads();
    #pragma unroll
    for (int j = 0; j < 4; j++) {
        int o = t + j*256;
        if (o < NLBL_) {
            float acc = 0.f;
            for (int k = 0; k < 512; k++) acc += ts[k] * Wc2[(size_t)k*NLBL_ + o];
            out[b*NLBL_ + o] = acc + bc2[o];
        }
    }
}

// ---------------- host orchestration ------------------------------------------
extern "C" void kernel_launch(void* const* d_in, const int* in_sizes, int n_in,
                              void* d_out, int out_size) {
    const float* x     = (const float*)d_in[0];
    const float* mask  = (const float*)d_in[1];
    const float* pos   = (const float*)d_in[2];
    const float* embln = (const float*)d_in[3];
    const float* Wq = (const float*)d_in[4];
    const float* bq = (const float*)d_in[5];
    const float* Wk = (const float*)d_in[6];
    const float* bk = (const float*)d_in[7];
    const float* Wv = (const float*)d_in[8];
    const float* bv = (const float*)d_in[9];
    const float* Wo = (const float*)d_in[10];
    const float* bo = (const float*)d_in[11];
    const float* ln1 = (const float*)d_in[12];
    const float* W1 = (const float*)d_in[13];
    const float* b1 = (const float*)d_in[14];
    const float* W2 = (const float*)d_in[15];
    const float* b2 = (const float*)d_in[16];
    const float* ln2 = (const float*)d_in[17];
    const float* Wc1 = (const float*)d_in[18];
    const float* bc1 = (const float*)d_in[19];
    const float* Wc2 = (const float*)d_in[20];
    const float* bc2 = (const float*)d_in[21];
    const int*   rnd = (const int*)d_in[22];
    float* out = (float*)d_out;

    float *ph, *pt, *pq, *pk, *pv, *pa, *pf;
    cudaGetSymbolAddress((void**)&ph, g_h);
    cudaGetSymbolAddress((void**)&pt, g_t);
    cudaGetSymbolAddress((void**)&pq, g_q);
    cudaGetSymbolAddress((void**)&pk, g_k);
    cudaGetSymbolAddress((void**)&pv, g_v);
    cudaGetSymbolAddress((void**)&pa, g_attn);
    cudaGetSymbolAddress((void**)&pf, g_ff);

    cudaFuncSetAttribute(attn_inner_kernel,  cudaFuncAttributeMaxDynamicSharedMemorySize, SMEM_INNER);
    cudaFuncSetAttribute(attn_global_kernel, cudaFuncAttributeMaxDynamicSharedMemorySize, SMEM_GLOB);

    // embed + LN
    embed_kernel<<<BS_, 256>>>(x, pos, embln, embln + D_);

    dim3 gD(D_/128, BS_/128);     // N=1024 GEMMs
    dim3 gF(FF_/128, BS_/128);    // N=4096 GEMM

    for (int l = 0; l < L_; l++) {
        const float* lWq = Wq + (size_t)l*D_*D_;
        const float* lWk = Wk + (size_t)l*D_*D_;
        const float* lWv = Wv + (size_t)l*D_*D_;
        const float* lWo = Wo + (size_t)l*D_*D_;
        const float* lW1 = W1 + (size_t)l*D_*FF_;
        const float* lW2 = W2 + (size_t)l*FF_*D_;

        sgemm_kernel<<<gD, 256>>>(ph, lWq, bq + (size_t)l*D_, nullptr, pq, BS_, D_, D_, 0);
        sgemm_kernel<<<gD, 256>>>(ph, lWk, bk + (size_t)l*D_, nullptr, pk, BS_, D_, D_, 0);
        sgemm_kernel<<<gD, 256>>>(ph, lWv, bv + (size_t)l*D_, nullptr, pv, BS_, D_, D_, 0);

        attn_inner_kernel<<<dim3(NI_, H_, B_), 256, SMEM_INNER>>>(mask, rnd);
        attn_global_kernel<<<dim3(4, 2, B_*H_), 256, SMEM_GLOB>>>(mask);

        // t = h + attn@Wo + bo ; LN1 in place
        sgemm_kernel<<<gD, 256>>>(pa, lWo, bo + (size_t)l*D_, ph, pt, BS_, D_, D_, 1);
        ln_kernel<<<BS_, 256>>>(pt, ln1 + (size_t)l*2*D_, ln1 + (size_t)l*2*D_ + D_);

        // ff = gelu(t@W1 + b1) ; h = t + ff@W2 + b2 ; LN2 in place
        sgemm_kernel<<<gF, 256>>>(pt, lW1, b1 + (size_t)l*FF_, nullptr, pf, BS_, FF_, D_, 2);
        sgemm_kernel<<<gD, 256>>>(pf, lW2, b2 + (size_t)l*D_, pt, ph, BS_, D_, FF_, 1);
        ln_kernel<<<BS_, 256>>>(ph, ln2 + (size_t)l*2*D_, ln2 + (size_t)l*2*D_ + D_);
    }

    cls1_kernel<<<B_, 512>>>(ph, Wc1, bc1);
    cls2_kernel<<<B_, 256>>>(Wc2, bc2, out);
}

// round 13
// speedup vs baseline: 1.0044x; 1.0015x over previous
#include <cuda_runtime.h>
#include <math.h>

#define B_  4
#define S_  1920
#define D_  1024
#define H_  8
#define L_  6
#define BLK_ 64
#define NB_ 30
#define NI_ 28
#define R_  3
#define FF_ 4096
#define DH_ 128
#define NLBL_ 1000
#define BS_ (B_*S_)
#define NEGF (-1.0e9f)

// ---------------- scratch (device globals; no allocation allowed) ------------
__device__ float g_h [(size_t)BS_*D_];
__device__ float g_t [(size_t)BS_*D_];
__device__ float g_q [(size_t)BS_*D_];
__device__ float g_k [(size_t)BS_*D_];
__device__ float g_v [(size_t)BS_*D_];
__device__ float g_attn[(size_t)BS_*D_];
__device__ float g_ff[(size_t)BS_*FF_];
__device__ float g_cls[B_*512];

// ---------------- helpers ----------------------------------------------------
__device__ __forceinline__ float gelu_f(float z) {
    // jax.nn.gelu approximate=True (tanh form)
    float z3 = z*z*z;
    return 0.5f*z*(1.0f + tanhf(0.7978845608028654f*(z + 0.044715f*z3)));
}

__device__ __forceinline__ float blockSum256(float v, float* red) {
    #pragma unroll
    for (int o = 16; o; o >>= 1) v += __shfl_xor_sync(0xffffffffu, v, o);
    __syncthreads();
    if ((threadIdx.x & 31) == 0) red[threadIdx.x >> 5] = v;
    __syncthreads();
    if (threadIdx.x == 0) {
        float t = 0.f;
        #pragma unroll
        for (int i = 0; i < 8; i++) t += red[i];
        red[8] = t;
    }
    __syncthreads();
    return red[8];
}

// ---------------- embedding: h = LN(x + pos_emb) ------------------------------
__global__ void embed_kernel(const float* __restrict__ x, const float* __restrict__ pos,
                             const float* __restrict__ gm, const float* __restrict__ bt) {
    __shared__ float red[9];
    int row = blockIdx.x;            // 0..BS_-1
    int s   = row % S_;
    const float* xr = x + (size_t)row*D_;
    const float* pr = pos + (size_t)s*D_;
    int t = threadIdx.x;             // 256 threads
    float v[4];
    #pragma unroll
    for (int j = 0; j < 4; j++) { int c = t + j*256; v[j] = xr[c] + pr[c]; }
    float su = v[0]+v[1]+v[2]+v[3];
    float mean = blockSum256(su, red) * (1.0f/(float)D_);
    float d[4], sq = 0.f;
    #pragma unroll
    for (int j = 0; j < 4; j++) { d[j] = v[j] - mean; sq += d[j]*d[j]; }
    float var = blockSum256(sq, red) * (1.0f/(float)D_);
    float rs = rsqrtf(var + 1e-12f);
    float* hr = g_h + (size_t)row*D_;
    #pragma unroll
    for (int j = 0; j < 4; j++) { int c = t + j*256; hr[c] = d[j]*rs*gm[c] + bt[c]; }
}

// ---------------- layernorm in place -----------------------------------------
__global__ void ln_kernel(float* __restrict__ x,
                          const float* __restrict__ gm, const float* __restrict__ bt) {
    __shared__ float red[9];
    int row = blockIdx.x;
    float* xr = x + (size_t)row*D_;
    int t = threadIdx.x;             // 256
    float v[4];
    #pragma unroll
    for (int j = 0; j < 4; j++) v[j] = xr[t + j*256];
    float su = v[0]+v[1]+v[2]+v[3];
    float mean = blockSum256(su, red) * (1.0f/(float)D_);
    float d[4], sq = 0.f;
    #pragma unroll
    for (int j = 0; j < 4; j++) { d[j] = v[j] - mean; sq += d[j]*d[j]; }
    float var = blockSum256(sq, red) * (1.0f/(float)D_);
    float rs = rsqrtf(var + 1e-12f);
    #pragma unroll
    for (int j = 0; j < 4; j++) { int c = t + j*256; xr[c] = d[j]*rs*gm[c] + bt[c]; }
}

// ---------------- SGEMM: C = A(MxK) @ Bw(KxN) + bias [+res | gelu] -----------
// BM=BN=128, BK=8, 256 threads, 8x8 micro-tile
__global__ __launch_bounds__(256, 2)
void sgemm_kernel(const float* __restrict__ A, const float* __restrict__ Bw,
                  const float* __restrict__ bias, const float* __restrict__ res,
                  float* __restrict__ C, int M, int N, int K, int epi) {
    __shared__ float As[8][132];
    __shared__ float Bs[8][128];
    int bm = blockIdx.y * 128, bn = blockIdx.x * 128;
    int tid = threadIdx.x;
    int arow = tid >> 1, acol = (tid & 1) << 2;
    int brow = tid >> 5, bcol = (tid & 31) << 2;
    int tx = tid & 15, ty = tid >> 4;
    const float* Ap = A + (size_t)(bm + arow)*K + acol;
    const float* Bp = Bw + (size_t)brow*N + bn + bcol;
    float acc[8][8];
    #pragma unroll
    for (int i = 0; i < 8; i++)
        #pragma unroll
        for (int j = 0; j < 8; j++) acc[i][j] = 0.f;
    int nk = K >> 3;
    for (int kt = 0; kt < nk; kt++) {
        float4 a4 = *(const float4*)Ap;
        float4 b4 = *(const float4*)Bp;
        As[acol+0][arow] = a4.x; As[acol+1][arow] = a4.y;
        As[acol+2][arow] = a4.z; As[acol+3][arow] = a4.w;
        *(float4*)&Bs[brow][bcol] = b4;
        __syncthreads();
        #pragma unroll
        for (int kk = 0; kk < 8; kk++) {
            float fa[8], fb[8];
            *(float4*)&fa[0] = *(const float4*)&As[kk][ty*8];
            *(float4*)&fa[4] = *(const float4*)&As[kk][ty*8+4];
            *(float4*)&fb[0] = *(const float4*)&Bs[kk][tx*8];
            *(float4*)&fb[4] = *(const float4*)&Bs[kk][tx*8+4];
            #pragma unroll
            for (int i = 0; i < 8; i++)
                #pragma unroll
                for (int j = 0; j < 8; j++)
                    acc[i][j] += fa[i]*fb[j];
        }
        __syncthreads();
        Ap += 8; Bp += (size_t)8*N;
    }
    #pragma unroll
    for (int i = 0; i < 8; i++) {
        int r = bm + ty*8 + i;
        size_t off = (size_t)r*N + bn + tx*8;
        #pragma unroll
        for (int j = 0; j < 8; j++) {
            int cidx = bn + tx*8 + j;
            float vv = acc[i][j] + bias[cidx];
            if (epi == 1)      vv += res[off + j];
            else if (epi == 2) vv = gelu_f(vv);
            C[off + j] = vv;
        }
    }
}

// ---------------- inner-block BigBird attention --------------------------------
// grid (NI_, H_, B_), 256 threads. Dynamic smem:
//   Qs 64x129 | KV 64x129 | Sc 64x516   = 49536 floats = 198144 B
#define SMEM_INNER (49536*4)
__global__ void attn_inner_kernel(const float* __restrict__ mask, const int* __restrict__ rnd) {
    extern __shared__ float sm[];
    float* Qs = sm;
    float* KV = sm + 64*129;
    float* Sc = sm + 2*64*129;
    __shared__ int   kblk[8];
    __shared__ float keepm[8];

    const int i = blockIdx.x, h = blockIdx.y, b = blockIdx.z;
    const int tid = threadIdx.x;
    const int tok0 = (i + 1) * BLK_;
    const float scale = 0.08838834764831845f;   // 1/sqrt(128)

    if (tid == 0) {
        int idx8[8];
        idx8[0] = 0; idx8[1] = NB_-1; idx8[2] = i; idx8[3] = i+1; idx8[4] = i+2;
        idx8[5] = rnd[(h*NI_ + i)*R_ + 0];
        idx8[6] = rnd[(h*NI_ + i)*R_ + 1];
        idx8[7] = rnd[(h*NI_ + i)*R_ + 2];
        #pragma unroll
        for (int j = 0; j < 8; j++) {
            float kp = 1.f;
            for (int j2 = 0; j2 < j; j2++) if (idx8[j2] == idx8[j]) kp = 0.f;
            kblk[j] = idx8[j]; keepm[j] = kp;
        }
    }
    // load Q (scaled)
    for (int t = tid; t < 64*32; t += 256) {
        int r = t >> 5, c = (t & 31) << 2;
        float4 v4 = *(const float4*)(g_q + ((size_t)(b*S_ + tok0 + r))*D_ + h*DH_ + c);
        float* dst = Qs + r*129 + c;
        dst[0] = v4.x*scale; dst[1] = v4.y*scale; dst[2] = v4.z*scale; dst[3] = v4.w*scale;
    }
    __syncthreads();

    const int ty = tid >> 4, tx = tid & 15;

    // ---- scores: 8 key blocks of 64 keys
    for (int jb = 0; jb < 8; jb++) {
        int kt0 = kblk[jb] * BLK_;
        for (int t = tid; t < 64*32; t += 256) {
            int r = t >> 5, c = (t & 31) << 2;
            float4 v4 = *(const float4*)(g_k + ((size_t)(b*S_ + kt0 + r))*D_ + h*DH_ + c);
            float* dst = KV + r*129 + c;
            dst[0] = v4.x; dst[1] = v4.y; dst[2] = v4.z; dst[3] = v4.w;
        }
        __syncthreads();
        float acc[4][4];
        #pragma unroll
        for (int a = 0; a < 4; a++)
            #pragma unroll
            for (int c2 = 0; c2 < 4; c2++) acc[a][c2] = 0.f;
        #pragma unroll 4
        for (int d = 0; d < 128; d++) {
            float fa[4], fb[4];
            #pragma unroll
            for (int u = 0; u < 4; u++) fa[u] = Qs[(ty*4+u)*129 + d];
            #pragma unroll
            for (int u = 0; u < 4; u++) fb[u] = KV[(tx*4+u)*129 + d];
            #pragma unroll
            for (int a = 0; a < 4; a++)
                #pragma unroll
                for (int c2 = 0; c2 < 4; c2++) acc[a][c2] += fa[a]*fb[c2];
        }
        float km = keepm[jb];
        #pragma unroll
        for (int c2 = 0; c2 < 4; c2++) {
            int kk = tx*4 + c2;
            float mg = km * mask[b*S_ + kt0 + kk];
            #pragma unroll
            for (int a = 0; a < 4; a++)
                Sc[(ty*4+a)*516 + jb*64 + kk] = (mg > 0.f) ? acc[a][c2] : NEGF;
        }
        __syncthreads();
    }

    // ---- softmax per row over 512 keys (4 threads per row)
    {
        int row = tid >> 2, l4 = tid & 3;
        float* Sr = Sc + row*516;
        float mx = -3.0e38f;
        for (int kk = l4; kk < 512; kk += 4) mx = fmaxf(mx, Sr[kk]);
        mx = fmaxf(mx, __shfl_xor_sync(0xffffffffu, mx, 1));
        mx = fmaxf(mx, __shfl_xor_sync(0xffffffffu, mx, 2));
        float su = 0.f;
        for (int kk = l4; kk < 512; kk += 4) {
            float p = __expf(Sr[kk] - mx);
            Sr[kk] = p; su += p;
        }
        su += __shfl_xor_sync(0xffffffffu, su, 1);
        su += __shfl_xor_sync(0xffffffffu, su, 2);
        float inv = 1.0f / su;
        for (int kk = l4; kk < 512; kk += 4) Sr[kk] *= inv;
    }
    __syncthreads();

    // ---- O = P @ V : 64x128, micro 4 rows x 8 cols
    float oacc[4][8];
    #pragma unroll
    for (int a = 0; a < 4; a++)
        #pragma unroll
        for (int c2 = 0; c2 < 8; c2++) oacc[a][c2] = 0.f;
    for (int jb = 0; jb < 8; jb++) {
        int kt0 = kblk[jb] * BLK_;
        for (int t = tid; t < 64*32; t += 256) {
            int r = t >> 5, c = (t & 31) << 2;
            float4 v4 = *(const float4*)(g_v + ((size_t)(b*S_ + kt0 + r))*D_ + h*DH_ + c);
            float* dst = KV + r*129 + c;
            dst[0] = v4.x; dst[1] = v4.y; dst[2] = v4.z; dst[3] = v4.w;
        }
        __syncthreads();
        #pragma unroll 2
        for (int kk = 0; kk < 64; kk++) {
            float pa[4], vb[8];
            #pragma unroll
            for (int u = 0; u < 4; u++) pa[u] = Sc[(ty*4+u)*516 + jb*64 + kk];
            #pragma unroll
            for (int u = 0; u < 8; u++) vb[u] = KV[kk*129 + tx*8 + u];
            #pragma unroll
            for (int a = 0; a < 4; a++)
                #pragma unroll
                for (int c2 = 0; c2 < 8; c2++) oacc[a][c2] += pa[a]*vb[c2];
        }
        __syncthreads();
    }
    #pragma unroll
    for (int a = 0; a < 4; a++) {
        int tok = tok0 + ty*4 + a;
        float* dst = g_attn + ((size_t)(b*S_ + tok))*D_ + h*DH_ + tx*8;
        #pragma unroll
        for (int c2 = 0; c2 < 8; c2++) dst[c2] = oacc[a][c2];
    }
}

// ---------------- global-block attention (flash over 30 chunks) ---------------
// grid (4 qsub, 2 g, B_*H_), 256 threads.
// smem: Qs 16x129 | Ks 64x129 | Vs 64x129 | Ss 16x68 | m/l/corr 16 each
#define SMEM_GLOB ((16*129 + 2*64*129 + 16*68 + 48)*4)
__global__ void attn_global_kernel(const float* __restrict__ mask) {
    extern __shared__ float sm[];
    float* Qs = sm;
    float* Ks = Qs + 16*129;
    float* Vs = Ks + 64*129;
    float* Ss = Vs + 64*129;
    float* mrow = Ss + 16*68;
    float* lrow = mrow + 16;
    float* crow = lrow + 16;

    const int qs = blockIdx.x;
    const int g  = blockIdx.y;
    const int b  = blockIdx.z >> 3, h = blockIdx.z & 7;
    const int tid = threadIdx.x;
    const int tok0 = (g == 0 ? 0 : (NB_-1)*BLK_) + qs*16;
    const float scale = 0.08838834764831845f;

    for (int t = tid; t < 16*32; t += 256) {
        int r = t >> 5, c = (t & 31) << 2;
        float4 v4 = *(const float4*)(g_q + ((size_t)(b*S_ + tok0 + r))*D_ + h*DH_ + c);
        float* dst = Qs + r*129 + c;
        dst[0] = v4.x*scale; dst[1] = v4.y*scale; dst[2] = v4.z*scale; dst[3] = v4.w*scale;
    }
    if (tid < 16) { mrow[tid] = -3.0e38f; lrow[tid] = 0.f; }
    __syncthreads();

    const int row = tid >> 4, tx = tid & 15;
    float oacc[8];
    #pragma unroll
    for (int u = 0; u < 8; u++) oacc[u] = 0.f;

    for (int cb = 0; cb < NB_; cb++) {
        int kt0 = cb * BLK_;
        for (int t = tid; t < 64*32; t += 256) {
            int r = t >> 5, c = (t & 31) << 2;
            size_t gi = ((size_t)(b*S_ + kt0 + r))*D_ + h*DH_ + c;
            float4 k4 = *(const float4*)(g_k + gi);
            float4 v4 = *(const float4*)(g_v + gi);
            float* dk = Ks + r*129 + c;
            float* dv = Vs + r*129 + c;
            dk[0]=k4.x; dk[1]=k4.y; dk[2]=k4.z; dk[3]=k4.w;
            dv[0]=v4.x; dv[1]=v4.y; dv[2]=v4.z; dv[3]=v4.w;
        }
        __syncthreads();
        // scores: each thread 1 row x 4 keys
        float sc4[4] = {0.f, 0.f, 0.f, 0.f};
        #pragma unroll 4
        for (int d = 0; d < 128; d++) {
            float qa = Qs[row*129 + d];
            #pragma unroll
            for (int u = 0; u < 4; u++) sc4[u] += qa * Ks[(tx*4+u)*129 + d];
        }
        #pragma unroll
        for (int u = 0; u < 4; u++) {
            int kk = tx*4 + u;
            float mg = mask[b*S_ + kt0 + kk];
            Ss[row*68 + kk] = (mg > 0.f) ? sc4[u] : NEGF;
        }
        __syncthreads();
        if (tid < 16) {
            float* Sr = Ss + tid*68;
            float cmax = -3.0e38f;
            for (int kk = 0; kk < 64; kk++) cmax = fmaxf(cmax, Sr[kk]);
            float m0 = mrow[tid];
            float nm = fmaxf(m0, cmax);
            float cr = __expf(m0 - nm);
            float sn = 0.f;
            for (int kk = 0; kk < 64; kk++) {
                float p = __expf(Sr[kk] - nm);
                Sr[kk] = p; sn += p;
            }
            lrow[tid] = lrow[tid]*cr + sn;
            mrow[tid] = nm;
            crow[tid] = cr;
        }
        __syncthreads();
        float cr = crow[row];
        #pragma unroll
        for (int u = 0; u < 8; u++) oacc[u] *= cr;
        #pragma unroll 2
        for (int kk = 0; kk < 64; kk++) {
            float p = Ss[row*68 + kk];
            #pragma unroll
            for (int u = 0; u < 8; u++) oacc[u] += p * Vs[kk*129 + tx*8 + u];
        }
        __syncthreads();
    }
    float inv = 1.0f / lrow[row];
    float* dst = g_attn + ((size_t)(b*S_ + tok0 + row))*D_ + h*DH_ + tx*8;
    #pragma unroll
    for (int u = 0; u < 8; u++) dst[u] = oacc[u]*inv;
}

// ---------------- classifier ---------------------------------------------------
__global__ void cls1_kernel(const float* __restrict__ hbuf, const float* __restrict__ Wc1,
                            const float* __restrict__ bc1) {
    __shared__ float hs[1024];
    int b = blockIdx.x, t = threadIdx.x;   // 512 threads
    hs[t]       = hbuf[((size_t)b*S_)*D_ + t];
    hs[t + 512] = hbuf[((size_t)b*S_)*D_ + t + 512];
    __syncthreads();
    float acc = 0.f;
    for (int k = 0; k < 1024; k++) acc += hs[k] * Wc1[(size_t)k*512 + t];
    acc += bc1[t];
    g_cls[b*512 + t] = fmaxf(acc, 0.f);
}

__global__ void cls2_kernel(const float* __restrict__ Wc2, const float* __restrict__ bc2,
                            float* __restrict__ out) {
    __shared__ float ts[512];
    int b = blockIdx.x, t = threadIdx.x;   // 256 threads
    ts[t]       = g_cls[b*512 + t];
    ts[t + 256] = g_cls[b*512 + t + 256];
    __syncthreads();
    #pragma unroll
    for (int j = 0; j < 4; j++) {
        int o = t + j*256;
        if (o < NLBL_) {
            float acc = 0.f;
            for (int k = 0; k < 512; k++) acc += ts[k] * Wc2[(size_t)k*NLBL_ + o];
            out[b*NLBL_ + o] = acc + bc2[o];
        }
    }
}

// ---------------- host orchestration ------------------------------------------
extern "C" void kernel_launch(void* const* d_in, const int* in_sizes, int n_in,
                              void* d_out, int out_size) {
    const float* x     = (const float*)d_in[0];
    const float* mask  = (const float*)d_in[1];
    const float* pos   = (const float*)d_in[2];
    const float* embln = (const float*)d_in[3];
    const float* Wq = (const float*)d_in[4];
    const float* bq = (const float*)d_in[5];
    const float* Wk = (const float*)d_in[6];
    const float* bk = (const float*)d_in[7];
    const float* Wv = (const float*)d_in[8];
    const float* bv = (const float*)d_in[9];
    const float* Wo = (const float*)d_in[10];
    const float* bo = (const float*)d_in[11];
    const float* ln1 = (const float*)d_in[12];
    const float* W1 = (const float*)d_in[13];
    const float* b1 = (const float*)d_in[14];
    const float* W2 = (const float*)d_in[15];
    const float* b2 = (const float*)d_in[16];
    const float* ln2 = (const float*)d_in[17];
    const float* Wc1 = (const float*)d_in[18];
    const float* bc1 = (const float*)d_in[19];
    const float* Wc2 = (const float*)d_in[20];
    const float* bc2 = (const float*)d_in[21];
    const int*   rnd = (const int*)d_in[22];
    float* out = (float*)d_out;

    float *ph, *pt, *pq, *pk, *pv, *pa, *pf;
    cudaGetSymbolAddress((void**)&ph, g_h);
    cudaGetSymbolAddress((void**)&pt, g_t);
    cudaGetSymbolAddress((void**)&pq, g_q);
    cudaGetSymbolAddress((void**)&pk, g_k);
    cudaGetSymbolAddress((void**)&pv, g_v);
    cudaGetSymbolAddress((void**)&pa, g_attn);
    cudaGetSymbolAddress((void**)&pf, g_ff);

    cudaFuncSetAttribute(attn_inner_kernel,  cudaFuncAttributeMaxDynamicSharedMemorySize, SMEM_INNER);
    cudaFuncSetAttribute(attn_global_kernel, cudaFuncAttributeMaxDynamicSharedMemorySize, SMEM_GLOB);

    // embed + LN
    embed_kernel<<<BS_, 256>>>(x, pos, embln, embln + D_);

    dim3 gD(D_/128, BS_/128);     // N=1024 GEMMs
    dim3 gF(FF_/128, BS_/128);    // N=4096 GEMM

    for (int l = 0; l < L_; l++) {
        const float* lWq = Wq + (size_t)l*D_*D_;
        const float* lWk = Wk + (size_t)l*D_*D_;
        const float* lWv = Wv + (size_t)l*D_*D_;
        const float* lWo = Wo + (size_t)l*D_*D_;
        const float* lW1 = W1 + (size_t)l*D_*FF_;
        const float* lW2 = W2 + (size_t)l*FF_*D_;

        sgemm_kernel<<<gD, 256>>>(ph, lWq, bq + (size_t)l*D_, nullptr, pq, BS_, D_, D_, 0);
        sgemm_kernel<<<gD, 256>>>(ph, lWk, bk + (size_t)l*D_, nullptr, pk, BS_, D_, D_, 0);
        sgemm_kernel<<<gD, 256>>>(ph, lWv, bv + (size_t)l*D_, nullptr, pv, BS_, D_, D_, 0);

        attn_inner_kernel<<<dim3(NI_, H_, B_), 256, SMEM_INNER>>>(mask, rnd);
        attn_global_kernel<<<dim3(4, 2, B_*H_), 256, SMEM_GLOB>>>(mask);

        // t = h + attn@Wo + bo ; LN1 in place
        sgemm_kernel<<<gD, 256>>>(pa, lWo, bo + (size_t)l*D_, ph, pt, BS_, D_, D_, 1);
        ln_kernel<<<BS_, 256>>>(pt, ln1 + (size_t)l*2*D_, ln1 + (size_t)l*2*D_ + D_);

        // ff = gelu(t@W1 + b1) ; h = t + ff@W2 + b2 ; LN2 in place
        sgemm_kernel<<<gF, 256>>>(pt, lW1, b1 + (size_t)l*FF_, nullptr, pf, BS_, FF_, D_, 2);
        sgemm_kernel<<<gD, 256>>>(pf, lW2, b2 + (size_t)l*D_, pt, ph, BS_, D_, FF_, 1);
        ln_kernel<<<BS_, 256>>>(ph, ln2 + (size_t)l*2*D_, ln2 + (size_t)l*2*D_ + D_);
    }

    cls1_kernel<<<B_, 512>>>(ph, Wc1, bc1);
    cls2_kernel<<<B_, 256>>>(Wc2, bc2, out);
}